// round 9
// baseline (speedup 1.0000x reference)
#include <cuda_runtime.h>
#include <cuda_fp16.h>
#include <cstdint>

// ---------------------------------------------------------------------------
// SmallMLP_INR: fused 6-layer MLP, base-target ISA (compute_103-safe).
// fp16 m16n8k16 mma.sync + ldmatrix. 64-row CTAs with 4 warps of 64x64 tiles;
// 2 CTAs co-resident per SM run decoupled so one CTA's MMAs cover the other's
// barriers/epilogues. Weights stream through a 2-slot XOR-swizzled ring.
// ---------------------------------------------------------------------------

#define THREADS 128
#define TILE_M  64
#define KDIM    256
#define NDIM    256

#define A_STRIDE 264       // halves; 528B rows -> ldmatrix conflict-free
#define SLOT_BYTES 32768   // 256 rows * 128B, XOR-swizzled

// SMEM layout (bytes)
#define SM_W1    0        // 512 f32
#define SM_B1    2048
#define SM_B2    3072
#define SM_B3    4096
#define SM_B4    5120
#define SM_B5    6144
#define SM_W6    7168
#define SM_B6    8192
#define SM_PART  8208     // 4*64 f32 = 1024
#define SM_A     9232     // 64*264*2 = 33792
#define SM_RING  43136    // 128-aligned; 2 * 32768 = 65536
#define SMEM_TOTAL 108672

// Pre-transposed fp16 weights: g_WtH[l][n*256 + k] = (half)W_{l+2}[k][n]
__device__ __half g_WtH[4][KDIM * NDIM];

// ---------------------------------------------------------------------------
__device__ __forceinline__ uint32_t smem_u32(const void* p) {
    uint32_t a;
    asm("{ .reg .u64 t; cvta.to.shared.u64 t, %1; cvt.u32.u64 %0, t; }" : "=r"(a) : "l"(p));
    return a;
}

__device__ __forceinline__ void mma_f16(float* c, const uint32_t* a, const uint32_t* b) {
    asm volatile(
        "mma.sync.aligned.m16n8k16.row.col.f32.f16.f16.f32 "
        "{%0,%1,%2,%3}, {%4,%5,%6,%7}, {%8,%9}, {%0,%1,%2,%3};\n"
        : "+f"(c[0]), "+f"(c[1]), "+f"(c[2]), "+f"(c[3])
        : "r"(a[0]), "r"(a[1]), "r"(a[2]), "r"(a[3]), "r"(b[0]), "r"(b[1]));
}

#define LDMATRIX_X4(r0, r1, r2, r3, addr) \
    asm volatile("ldmatrix.sync.aligned.m8n8.x4.shared.b16 {%0,%1,%2,%3}, [%4];" \
                 : "=r"(r0), "=r"(r1), "=r"(r2), "=r"(r3) : "r"(addr))

__device__ __forceinline__ void cp_async16(uint32_t dst, const void* src) {
    asm volatile("cp.async.cg.shared.global [%0], [%1], 16;" :: "r"(dst), "l"(src) : "memory");
}
__device__ __forceinline__ void cp_commit() { asm volatile("cp.async.commit_group;" ::: "memory"); }
__device__ __forceinline__ void cp_wait1()  { asm volatile("cp.async.wait_group 1;" ::: "memory"); }
__device__ __forceinline__ void cp_wait0()  { asm volatile("cp.async.wait_group 0;" ::: "memory"); }

// CTA-wide (128 thr): one 256x64 weight chunk (32KB) into a ring slot.
// Rows are 128B, XOR-swizzled in 16B segments: seg_phys = seg ^ (row & 7).
__device__ __forceinline__ void load_chunk(uint32_t slot, const __half* Wt,
                                           int c, int tid) {
#pragma unroll
    for (int h = 0; h < 2; h++) {
        const int row = tid + h * 128;
        const uint32_t dst = slot + (uint32_t)row * 128;
        const uint32_t rx = (uint32_t)(row & 7);
        const __half* src = Wt + (size_t)row * KDIM + c * 64;
#pragma unroll
        for (uint32_t j = 0; j < 8; j++)
            cp_async16(dst + ((j ^ rx) << 4), src + j * 8);
    }
    cp_commit();
}

// ---------------------------------------------------------------------------
// weight pre-transpose + fp16 round
// ---------------------------------------------------------------------------
__global__ void transpose_w_kernel(const float* __restrict__ W2, const float* __restrict__ W3,
                                   const float* __restrict__ W4, const float* __restrict__ W5) {
    __shared__ float t[32][33];
    const float* W = (blockIdx.z == 0) ? W2 : (blockIdx.z == 1) ? W3
                   : (blockIdx.z == 2) ? W4 : W5;
    const int nb = blockIdx.x * 32, kb = blockIdx.y * 32;
    const int tx = threadIdx.x, ty = threadIdx.y;
#pragma unroll
    for (int i = 0; i < 32; i += 8)
        t[ty + i][tx] = W[(size_t)(kb + ty + i) * 256 + (nb + tx)];
    __syncthreads();
    __half* dst = g_WtH[blockIdx.z];
#pragma unroll
    for (int i = 0; i < 32; i += 8)
        dst[(size_t)(nb + ty + i) * 256 + (kb + tx)] = __float2half_rn(t[tx][ty + i]);
}

// ---------------------------------------------------------------------------
// main fused kernel: one CTA = 64 rows; warp = 64M x 64N tile; 2 CTAs/SM
// ---------------------------------------------------------------------------
__global__ void __launch_bounds__(THREADS, 2) mlp_kernel(
    const float* __restrict__ coords,
    const float* __restrict__ W1, const float* __restrict__ b1,
    const float* __restrict__ b2, const float* __restrict__ b3,
    const float* __restrict__ b4, const float* __restrict__ b5,
    const float* __restrict__ W6, const float* __restrict__ b6,
    float* __restrict__ out) {
    extern __shared__ __align__(128) char smem[];
    const uint32_t sb = smem_u32(smem);
    const int tid = threadIdx.x;
    const int wid = tid >> 5;
    const int lid = tid & 31;
    const int g = lid >> 2;
    const int t = lid & 3;
    const int ncol = wid * 64;           // this warp's 64-col N slice
    const int row_base = blockIdx.x * TILE_M;

    float* sW1 = (float*)(smem + SM_W1);
    float* sB1 = (float*)(smem + SM_B1);
    float* sB2 = (float*)(smem + SM_B2);
    float* sB3 = (float*)(smem + SM_B3);
    float* sB4 = (float*)(smem + SM_B4);
    float* sB5 = (float*)(smem + SM_B5);
    float* sW6 = (float*)(smem + SM_W6);
    float* sB6 = (float*)(smem + SM_B6);
    float* sPart = (float*)(smem + SM_PART);
    __half* sA = (__half*)(smem + SM_A);
    const uint32_t rb = sb + SM_RING;

    // stage small params (128 threads -> 2 elems each for 256-vectors)
    sW1[tid]       = W1[tid];
    sW1[tid + 128] = W1[tid + 128];
    sW1[tid + 256] = W1[tid + 256];
    sW1[tid + 384] = W1[tid + 384];
    sB1[tid] = b1[tid];       sB1[tid + 128] = b1[tid + 128];
    sB2[tid] = b2[tid];       sB2[tid + 128] = b2[tid + 128];
    sB3[tid] = b3[tid];       sB3[tid + 128] = b3[tid + 128];
    sB4[tid] = b4[tid];       sB4[tid + 128] = b4[tid + 128];
    sB5[tid] = b5[tid];       sB5[tid + 128] = b5[tid + 128];
    sW6[tid] = W6[tid];       sW6[tid + 128] = W6[tid + 128];
    if (tid == 0) sB6[0] = b6[0];

    // prologue: prefetch chunks 0,1 of layer 2
    load_chunk(rb,              g_WtH[0], 0, tid);
    load_chunk(rb + SLOT_BYTES, g_WtH[0], 1, tid);

    __syncthreads();

    // ---- Layer 1 (fan-in 2, FFMA) -> sA (fp16) ----
    {
        const int row = tid >> 1;
        const int j0  = (tid & 1) * 128;
        const float2 c = *(const float2*)(coords + 2 * (size_t)(row_base + row));
        __half* dst = sA + (size_t)row * A_STRIDE;
#pragma unroll
        for (int j = 0; j < 128; j += 2) {
            const int jj = j0 + j;
            float v0 = fmaxf(fmaf(c.x, sW1[jj + 0], fmaf(c.y, sW1[256 + jj + 0], sB1[jj + 0])), 0.f);
            float v1 = fmaxf(fmaf(c.x, sW1[jj + 1], fmaf(c.y, sW1[256 + jj + 1], sB1[jj + 1])), 0.f);
            *(__half2*)(dst + jj) = __floats2half2_rn(v0, v1);
        }
    }

    // ldmatrix lane-address bases
    // A: lanes 0-7 rows 0..7 @k | 8-15 rows 8..15 @k | 16-23 rows 0..7 @k+8 | 24-31 rows 8..15 @k+8
    const uint32_t aA = sb + SM_A +
        (uint32_t)(((lid & 15) * A_STRIDE + ((lid & 16) ? 8 : 0)) * 2);
    // B (XOR-swizzled 128B rows): n-row = ncol + (lid&7) + (lid&16 ? 8:0),
    // 16B segment (2*ks + b8) ^ (row&7)
    const int brow = ncol + (lid & 7) + ((lid & 16) ? 8 : 0);
    const uint32_t bRow = (uint32_t)brow * 128;
    const uint32_t brx = (uint32_t)(lid & 7);
    const uint32_t b8 = (uint32_t)((lid >> 3) & 1);

    // ---- Layers 2..5: flat 16-chunk pipeline, 2-slot ring ----
#pragma unroll 1
    for (int l = 0; l < 4; l++) {
        float acc[4][8][4];
#pragma unroll
        for (int i = 0; i < 4; i++)
#pragma unroll
            for (int j = 0; j < 8; j++)
#pragma unroll
                for (int c = 0; c < 4; c++) acc[i][j][c] = 0.f;

#pragma unroll
        for (int c = 0; c < 4; c++) {
            const int f = l * 4 + c;
            if (f == 15) cp_wait0(); else cp_wait1();
            __syncthreads();

            const uint32_t slot = rb + (uint32_t)(f & 1) * SLOT_BYTES;
#pragma unroll
            for (int ks = 0; ks < 4; ks++) {
                const int k0 = c * 64 + ks * 16;   // k offset in sA (halves)
                const uint32_t soff = ((((uint32_t)(2 * ks) + b8) ^ brx) << 4);
                uint32_t b[4][4];
#pragma unroll
                for (int jp = 0; jp < 4; jp++)
                    LDMATRIX_X4(b[jp][0], b[jp][1], b[jp][2], b[jp][3],
                                slot + bRow + (uint32_t)jp * (16 * 128) + soff);
#pragma unroll
                for (int i = 0; i < 4; i++) {
                    uint32_t a[4];
                    LDMATRIX_X4(a[0], a[1], a[2], a[3],
                                aA + (uint32_t)(i * 16 * A_STRIDE + k0) * 2);
#pragma unroll
                    for (int j = 0; j < 8; j++)
                        mma_f16(acc[i][j], a, &b[j >> 1][(j & 1) * 2]);
                }
            }

            __syncthreads();   // all warps done reading this slot (and sA)

            const int q = f + 2;
            if (q < 16)
                load_chunk(rb + (uint32_t)(q & 1) * SLOT_BYTES, g_WtH[q >> 2],
                           q & 3, tid);
        }

        if (l < 3) {
            // epilogue: sA <- (half)relu(D + bias) for this warp's 64 cols
            const float* bias = (l == 0) ? sB2 : (l == 1) ? sB3 : sB4;
#pragma unroll
            for (int j = 0; j < 8; j++) {
                const int col = ncol + 8 * j + 2 * t;
                const float bs0 = bias[col], bs1 = bias[col + 1];
#pragma unroll
                for (int i = 0; i < 4; i++) {
                    const int row = 16 * i + g;
                    *(__half2*)(sA + (size_t)row * A_STRIDE + col) =
                        __floats2half2_rn(fmaxf(acc[i][j][0] + bs0, 0.f),
                                          fmaxf(acc[i][j][1] + bs1, 0.f));
                    *(__half2*)(sA + (size_t)(row + 8) * A_STRIDE + col) =
                        __floats2half2_rn(fmaxf(acc[i][j][2] + bs0, 0.f),
                                          fmaxf(acc[i][j][3] + bs1, 0.f));
                }
            }
            // next chunk's arrival __syncthreads orders writes before reads
        } else {
            // ---- Layer 6: out = relu(D + b5) . W6 + b6 ----
            float r0[4] = {0.f, 0.f, 0.f, 0.f};
            float r1[4] = {0.f, 0.f, 0.f, 0.f};
#pragma unroll
            for (int j = 0; j < 8; j++) {
                const int col = ncol + 8 * j + 2 * t;
                const float w0 = sW6[col], w1 = sW6[col + 1];
                const float s0 = sB5[col], s1 = sB5[col + 1];
#pragma unroll
                for (int i = 0; i < 4; i++) {
                    r0[i] = fmaf(fmaxf(acc[i][j][0] + s0, 0.f), w0, r0[i]);
                    r0[i] = fmaf(fmaxf(acc[i][j][1] + s1, 0.f), w1, r0[i]);
                    r1[i] = fmaf(fmaxf(acc[i][j][2] + s0, 0.f), w0, r1[i]);
                    r1[i] = fmaf(fmaxf(acc[i][j][3] + s1, 0.f), w1, r1[i]);
                }
            }
#pragma unroll
            for (int d = 1; d <= 2; d <<= 1) {
#pragma unroll
                for (int i = 0; i < 4; i++) {
                    r0[i] += __shfl_xor_sync(0xFFFFFFFFu, r0[i], d);
                    r1[i] += __shfl_xor_sync(0xFFFFFFFFu, r1[i], d);
                }
            }
            if (t == 0) {
                float* part = sPart + wid * 64;
#pragma unroll
                for (int i = 0; i < 4; i++) {
                    part[16 * i + g]     = r0[i];
                    part[16 * i + g + 8] = r1[i];
                }
            }
            __syncthreads();
            if (tid < TILE_M)
                out[row_base + tid] = sPart[tid] + sPart[64 + tid] +
                                      sPart[128 + tid] + sPart[192 + tid] + sB6[0];
        }
    }
}

// ---------------------------------------------------------------------------
extern "C" void kernel_launch(void* const* d_in, const int* in_sizes, int n_in,
                              void* d_out, int out_size) {
    const float* coords = (const float*)d_in[0];
    const float* W1 = (const float*)d_in[1];
    const float* b1 = (const float*)d_in[2];
    const float* W2 = (const float*)d_in[3];
    const float* b2 = (const float*)d_in[4];
    const float* W3 = (const float*)d_in[5];
    const float* b3 = (const float*)d_in[6];
    const float* W4 = (const float*)d_in[7];
    const float* b4 = (const float*)d_in[8];
    const float* W5 = (const float*)d_in[9];
    const float* b5 = (const float*)d_in[10];
    const float* W6 = (const float*)d_in[11];
    const float* b6 = (const float*)d_in[12];
    float* out = (float*)d_out;

    const int n = in_sizes[0] / 2;  // rows

    transpose_w_kernel<<<dim3(NDIM / 32, KDIM / 32, 4), dim3(32, 8)>>>(W2, W3, W4, W5);

    cudaFuncSetAttribute(mlp_kernel, cudaFuncAttributeMaxDynamicSharedMemorySize, SMEM_TOTAL);
    mlp_kernel<<<n / TILE_M, THREADS, SMEM_TOTAL>>>(coords, W1, b1, b2, b3, b4, b5,
                                                    W6, b6, out);
}

// round 10
// speedup vs baseline: 1.4044x; 1.4044x over previous
#include <cuda_runtime.h>
#include <cuda_fp16.h>
#include <cstdint>

// ---------------------------------------------------------------------------
// SmallMLP_INR: fused 6-layer MLP, base-target ISA (compute_103-safe).
// fp16 m16n8k16 mma.sync + ldmatrix. TILE_M=128, 8 warps of 64x64 tiles.
// B is pair-shared: each pair of warps (same N-slice) owns a private 4-slot
// cp.async ring synced with 2-warp named barriers — no CTA-wide barriers in
// the mainloop, so the 4 pairs run decoupled and hide each other's stalls.
// ---------------------------------------------------------------------------

#define THREADS 256
#define TILE_M  128
#define KDIM    256
#define NDIM    256

#define A_STRIDE 264       // halves; 528B rows -> ldmatrix conflict-free
#define SLOT_BYTES 8192    // 64 rows * 128B, XOR-swizzled
#define PAIR_RING  32768   // 4 slots

// SMEM layout (bytes)
#define SM_W1    0        // 512 f32
#define SM_B1    2048
#define SM_B2    3072
#define SM_B3    4096
#define SM_B4    5120
#define SM_B5    6144
#define SM_W6    7168
#define SM_B6    8192
#define SM_PART  8208     // 4*128 f32 = 2048
#define SM_A     10496    // 128*264*2 = 67584
#define SM_RING  78080    // 4 pairs * 32768 = 131072
#define SMEM_TOTAL 209152

// Pre-transposed fp16 weights: g_WtH[l][n*256 + k] = (half)W_{l+2}[k][n]
__device__ __half g_WtH[4][KDIM * NDIM];

// ---------------------------------------------------------------------------
__device__ __forceinline__ uint32_t smem_u32(const void* p) {
    uint32_t a;
    asm("{ .reg .u64 t; cvta.to.shared.u64 t, %1; cvt.u32.u64 %0, t; }" : "=r"(a) : "l"(p));
    return a;
}

__device__ __forceinline__ void mma_f16(float* c, const uint32_t* a, const uint32_t* b) {
    asm volatile(
        "mma.sync.aligned.m16n8k16.row.col.f32.f16.f16.f32 "
        "{%0,%1,%2,%3}, {%4,%5,%6,%7}, {%8,%9}, {%0,%1,%2,%3};\n"
        : "+f"(c[0]), "+f"(c[1]), "+f"(c[2]), "+f"(c[3])
        : "r"(a[0]), "r"(a[1]), "r"(a[2]), "r"(a[3]), "r"(b[0]), "r"(b[1]));
}

#define LDMATRIX_X4(r0, r1, r2, r3, addr) \
    asm volatile("ldmatrix.sync.aligned.m8n8.x4.shared.b16 {%0,%1,%2,%3}, [%4];" \
                 : "=r"(r0), "=r"(r1), "=r"(r2), "=r"(r3) : "r"(addr))

__device__ __forceinline__ void cp_async16(uint32_t dst, const void* src) {
    asm volatile("cp.async.cg.shared.global [%0], [%1], 16;" :: "r"(dst), "l"(src) : "memory");
}
__device__ __forceinline__ void cp_commit() { asm volatile("cp.async.commit_group;" ::: "memory"); }
__device__ __forceinline__ void cp_wait2()  { asm volatile("cp.async.wait_group 2;" ::: "memory"); }
__device__ __forceinline__ void cp_wait1()  { asm volatile("cp.async.wait_group 1;" ::: "memory"); }
__device__ __forceinline__ void cp_wait0()  { asm volatile("cp.async.wait_group 0;" ::: "memory"); }

// 2-warp named barrier for pair p (ids 1..4, 64 threads)
__device__ __forceinline__ void bar_pair(int p) {
    asm volatile("bar.sync %0, %1;" :: "r"(1 + p), "r"(64) : "memory");
}

// Pair-cooperative: load one 64x64 B chunk (8KB) into a pair ring slot.
// Warp (wid&1)==0 loads local rows 0..31, ==1 loads 32..63. Rows are 128B,
// XOR-swizzled in 16B segments: seg_phys = seg ^ (row & 7).
__device__ __forceinline__ void load_pchunk(uint32_t slot, const __half* Wt,
                                            int ncol, int c, int half, int lid) {
    const int rloc = half * 32 + lid;
    const uint32_t dst = slot + (uint32_t)rloc * 128;
    const uint32_t rx = (uint32_t)(rloc & 7);
    const __half* src = Wt + (size_t)(ncol + rloc) * KDIM + c * 64;
#pragma unroll
    for (uint32_t j = 0; j < 8; j++)
        cp_async16(dst + ((j ^ rx) << 4), src + j * 8);
    cp_commit();
}

// ---------------------------------------------------------------------------
// weight pre-transpose + fp16 round
// ---------------------------------------------------------------------------
__global__ void transpose_w_kernel(const float* __restrict__ W2, const float* __restrict__ W3,
                                   const float* __restrict__ W4, const float* __restrict__ W5) {
    __shared__ float t[32][33];
    const float* W = (blockIdx.z == 0) ? W2 : (blockIdx.z == 1) ? W3
                   : (blockIdx.z == 2) ? W4 : W5;
    const int nb = blockIdx.x * 32, kb = blockIdx.y * 32;
    const int tx = threadIdx.x, ty = threadIdx.y;
#pragma unroll
    for (int i = 0; i < 32; i += 8)
        t[ty + i][tx] = W[(size_t)(kb + ty + i) * 256 + (nb + tx)];
    __syncthreads();
    __half* dst = g_WtH[blockIdx.z];
#pragma unroll
    for (int i = 0; i < 32; i += 8)
        dst[(size_t)(nb + ty + i) * 256 + (kb + tx)] = __float2half_rn(t[tx][ty + i]);
}

// ---------------------------------------------------------------------------
// main fused kernel: one CTA = 128 rows; warp = 64M x 64N; pair-shared B
// ---------------------------------------------------------------------------
__global__ void __launch_bounds__(THREADS, 1) mlp_kernel(
    const float* __restrict__ coords,
    const float* __restrict__ W1, const float* __restrict__ b1,
    const float* __restrict__ b2, const float* __restrict__ b3,
    const float* __restrict__ b4, const float* __restrict__ b5,
    const float* __restrict__ W6, const float* __restrict__ b6,
    float* __restrict__ out) {
    extern __shared__ __align__(128) char smem[];
    const uint32_t sb = smem_u32(smem);
    const int tid = threadIdx.x;
    const int wid = tid >> 5;
    const int lid = tid & 31;
    const int g = lid >> 2;
    const int t = lid & 3;
    const int half = wid & 1;            // M half within pair
    const int pair = wid >> 1;           // 0..3
    const int mrow = half * 64;
    const int ncol = pair * 64;
    const int row_base = blockIdx.x * TILE_M;

    float* sW1 = (float*)(smem + SM_W1);
    float* sB1 = (float*)(smem + SM_B1);
    float* sB2 = (float*)(smem + SM_B2);
    float* sB3 = (float*)(smem + SM_B3);
    float* sB4 = (float*)(smem + SM_B4);
    float* sB5 = (float*)(smem + SM_B5);
    float* sW6 = (float*)(smem + SM_W6);
    float* sB6 = (float*)(smem + SM_B6);
    float* sPart = (float*)(smem + SM_PART);
    __half* sA = (__half*)(smem + SM_A);
    const uint32_t ring = sb + SM_RING + (uint32_t)pair * PAIR_RING;

    // stage small params
    sW1[tid]       = W1[tid];
    sW1[tid + 256] = W1[tid + 256];
    sB1[tid] = b1[tid];
    sB2[tid] = b2[tid];
    sB3[tid] = b3[tid];
    sB4[tid] = b4[tid];
    sB5[tid] = b5[tid];
    sW6[tid] = W6[tid];
    if (tid == 0) sB6[0] = b6[0];

    // prologue: pair prefetches its chunks 0..2 of layer 2 (slots 0..2)
    load_pchunk(ring,                  g_WtH[0], ncol, 0, half, lid);
    load_pchunk(ring + SLOT_BYTES,     g_WtH[0], ncol, 1, half, lid);
    load_pchunk(ring + 2 * SLOT_BYTES, g_WtH[0], ncol, 2, half, lid);

    __syncthreads();

    // ---- Layer 1 (fan-in 2, FFMA) -> sA (fp16) ----
    {
        const int row = tid >> 1;
        const int j0  = (tid & 1) * 128;
        const float2 c = *(const float2*)(coords + 2 * (size_t)(row_base + row));
        __half* dst = sA + (size_t)row * A_STRIDE;
#pragma unroll
        for (int j = 0; j < 128; j += 2) {
            const int jj = j0 + j;
            float v0 = fmaxf(fmaf(c.x, sW1[jj + 0], fmaf(c.y, sW1[256 + jj + 0], sB1[jj + 0])), 0.f);
            float v1 = fmaxf(fmaf(c.x, sW1[jj + 1], fmaf(c.y, sW1[256 + jj + 1], sB1[jj + 1])), 0.f);
            *(__half2*)(dst + jj) = __floats2half2_rn(v0, v1);
        }
    }
    __syncthreads();   // sA ready for all warps

    // ldmatrix lane-address bases
    // A: lanes 0-7 rows 0..7 @k | 8-15 rows 8..15 @k | 16-23 rows 0..7 @k+8 | 24-31 rows 8..15 @k+8
    const uint32_t aA = sb + SM_A +
        (uint32_t)(((mrow + (lid & 15)) * A_STRIDE + ((lid & 16) ? 8 : 0)) * 2);
    // B (XOR-swizzled 128B rows in 64-row slots): local row = (lid&7)+((lid&16)?8:0)+jp*16;
    // 16B segment (2*ks + b8) ^ (lid&7)
    const uint32_t bRow = (uint32_t)((lid & 7) + ((lid & 16) ? 8 : 0)) * 128;
    const uint32_t brx = (uint32_t)(lid & 7);
    const uint32_t b8 = (uint32_t)((lid >> 3) & 1);

    // ---- Layers 2..5: flat 16-chunk per-pair pipeline, slot index == f&3 ----
#pragma unroll 1
    for (int l = 0; l < 4; l++) {
        float acc[4][8][4];
#pragma unroll
        for (int i = 0; i < 4; i++)
#pragma unroll
            for (int j = 0; j < 8; j++)
#pragma unroll
                for (int c = 0; c < 4; c++) acc[i][j][c] = 0.f;

#pragma unroll
        for (int c = 0; c < 4; c++) {
            const int f = l * 4 + c;
            if (l == 3 && c == 2)      cp_wait1();
            else if (l == 3 && c == 3) cp_wait0();
            else                       cp_wait2();
            bar_pair(pair);   // both warps: chunk f visible, chunk f-1 reads done

            // prefetch chunk f+3 into slot (f+3)&3 (the slot chunk f-1 used)
            const int q = f + 3;
            if (q < 16)
                load_pchunk(ring + (uint32_t)(q & 3) * SLOT_BYTES,
                            g_WtH[q >> 2], ncol, q & 3, half, lid);

            const uint32_t slot = ring + (uint32_t)(f & 3) * SLOT_BYTES;
#pragma unroll
            for (int ks = 0; ks < 4; ks++) {
                const int k0 = c * 64 + ks * 16;   // k offset in sA (halves)
                const uint32_t soff = ((((uint32_t)(2 * ks) + b8) ^ brx) << 4);
                uint32_t b[4][4];
#pragma unroll
                for (int jp = 0; jp < 4; jp++)
                    LDMATRIX_X4(b[jp][0], b[jp][1], b[jp][2], b[jp][3],
                                slot + bRow + (uint32_t)jp * (16 * 128) + soff);
#pragma unroll
                for (int i = 0; i < 4; i++) {
                    uint32_t a[4];
                    LDMATRIX_X4(a[0], a[1], a[2], a[3],
                                aA + (uint32_t)(i * 16 * A_STRIDE + k0) * 2);
#pragma unroll
                    for (int j = 0; j < 8; j++)
                        mma_f16(acc[i][j], a, &b[j >> 1][(j & 1) * 2]);
                }
            }
        }

        __syncthreads();   // all warps done reading sA this layer

        if (l < 3) {
            // epilogue: sA <- (half)relu(D + bias) for this warp's 64x64 tile
            const float* bias = (l == 0) ? sB2 : (l == 1) ? sB3 : sB4;
#pragma unroll
            for (int j = 0; j < 8; j++) {
                const int col = ncol + 8 * j + 2 * t;
                const float bs0 = bias[col], bs1 = bias[col + 1];
#pragma unroll
                for (int i = 0; i < 4; i++) {
                    const int row = mrow + 16 * i + g;
                    *(__half2*)(sA + (size_t)row * A_STRIDE + col) =
                        __floats2half2_rn(fmaxf(acc[i][j][0] + bs0, 0.f),
                                          fmaxf(acc[i][j][1] + bs1, 0.f));
                    *(__half2*)(sA + (size_t)(row + 8) * A_STRIDE + col) =
                        __floats2half2_rn(fmaxf(acc[i][j][2] + bs0, 0.f),
                                          fmaxf(acc[i][j][3] + bs1, 0.f));
                }
            }
            __syncthreads();   // sA consistent before next layer's reads
        } else {
            // ---- Layer 6: out = relu(D + b5) . W6 + b6 ----
            float r0[4] = {0.f, 0.f, 0.f, 0.f};
            float r1[4] = {0.f, 0.f, 0.f, 0.f};
#pragma unroll
            for (int j = 0; j < 8; j++) {
                const int col = ncol + 8 * j + 2 * t;
                const float w0 = sW6[col], w1 = sW6[col + 1];
                const float s0 = sB5[col], s1 = sB5[col + 1];
#pragma unroll
                for (int i = 0; i < 4; i++) {
                    r0[i] = fmaf(fmaxf(acc[i][j][0] + s0, 0.f), w0, r0[i]);
                    r0[i] = fmaf(fmaxf(acc[i][j][1] + s1, 0.f), w1, r0[i]);
                    r1[i] = fmaf(fmaxf(acc[i][j][2] + s0, 0.f), w0, r1[i]);
                    r1[i] = fmaf(fmaxf(acc[i][j][3] + s1, 0.f), w1, r1[i]);
                }
            }
#pragma unroll
            for (int d = 1; d <= 2; d <<= 1) {
#pragma unroll
                for (int i = 0; i < 4; i++) {
                    r0[i] += __shfl_xor_sync(0xFFFFFFFFu, r0[i], d);
                    r1[i] += __shfl_xor_sync(0xFFFFFFFFu, r1[i], d);
                }
            }
            if (t == 0) {
                float* part = sPart + pair * 128;
#pragma unroll
                for (int i = 0; i < 4; i++) {
                    part[mrow + 16 * i + g]     = r0[i];
                    part[mrow + 16 * i + g + 8] = r1[i];
                }
            }
            __syncthreads();
            if (tid < TILE_M)
                out[row_base + tid] = sPart[tid] + sPart[128 + tid] +
                                      sPart[256 + tid] + sPart[384 + tid] + sB6[0];
        }
    }
}

// ---------------------------------------------------------------------------
extern "C" void kernel_launch(void* const* d_in, const int* in_sizes, int n_in,
                              void* d_out, int out_size) {
    const float* coords = (const float*)d_in[0];
    const float* W1 = (const float*)d_in[1];
    const float* b1 = (const float*)d_in[2];
    const float* W2 = (const float*)d_in[3];
    const float* b2 = (const float*)d_in[4];
    const float* W3 = (const float*)d_in[5];
    const float* b3 = (const float*)d_in[6];
    const float* W4 = (const float*)d_in[7];
    const float* b4 = (const float*)d_in[8];
    const float* W5 = (const float*)d_in[9];
    const float* b5 = (const float*)d_in[10];
    const float* W6 = (const float*)d_in[11];
    const float* b6 = (const float*)d_in[12];
    float* out = (float*)d_out;

    const int n = in_sizes[0] / 2;  // rows

    transpose_w_kernel<<<dim3(NDIM / 32, KDIM / 32, 4), dim3(32, 8)>>>(W2, W3, W4, W5);

    cudaFuncSetAttribute(mlp_kernel, cudaFuncAttributeMaxDynamicSharedMemorySize, SMEM_TOTAL);
    mlp_kernel<<<n / TILE_M, THREADS, SMEM_TOTAL>>>(coords, W1, b1, b2, b3, b4, b5,
                                                    W6, b6, out);
}